// round 16
// baseline (speedup 1.0000x reference)
#include <cuda_runtime.h>

// QPSK modulator: bits (256,16384) int32 -> Gray QPSK -> x16 zero-stuff
// (offset 8) -> RRC (K=128) -> out (256, 131072, 2) float32.
//
// Polyphase: y[16q+p] = sum_{i=0..7} sym[q+jmin+i] * rrc[k0+16i],
//   k0 = (71-p)&15, jmin = (p<=7) ? -4 : -3, scaled by sqrt(16).
// Symbols +-1/sqrt2 -> each output is one of 256 signed-tap sums per phase.
// Within a phase QUAD (p0 in {0,4,8,12}) window/flag/pattern are identical
// -> table T4[quad][pattern] of float4. Mainloop: ballot sign bits ->
// funnel-shift pattern -> 2x LDS.128 -> ONE st.global.cs.v8.b32 (32B/lane,
// warp writes 1KB dense per instruction; sm_103a supports 256-bit st).
// Write-path map: default 47.6-49us, wt 49.2us, .cs 41.4us (champion).
// R15 tests whether halving L2 write requests via STG.256 moves the
// 6.5 TB/s drain floor.

#define B_ROWS     256
#define NUM_BITS   16384
#define NS         8192
#define SPS        16
#define UP_LEN     (NS * SPS)          // 131072
#define SCALE      2.82842712474619f   // sqrt(16)/sqrt(2)

#define SYMS_PER_BLOCK   512
#define OUTS_PER_BLOCK   (SYMS_PER_BLOCK * SPS)     // 8192 complex
#define THREADS          256
#define ITS              8                          // quads per thread
#define TILES            (UP_LEN / OUTS_PER_BLOCK)  // 16
#define TROW4            257                        // padded float4 row stride
#define NWORDS           18                         // 520 sign bits

typedef unsigned long long ull;

__device__ __forceinline__ ull pack2(float lo, float hi) {
    ull v;
    asm("mov.b64 %0, {%1, %2};" : "=l"(v) : "f"(lo), "f"(hi));
    return v;
}

// 32B streaming store: 4 complex outputs, one instruction.
__device__ __forceinline__ void stcs8(void* p, float4 vr, float4 vi) {
    asm volatile(
        "st.global.cs.v8.b32 [%0], {%1, %2, %3, %4, %5, %6, %7, %8};"
        :: "l"(p), "f"(vr.x), "f"(vi.x), "f"(vr.y), "f"(vi.y),
           "f"(vr.z), "f"(vi.z), "f"(vr.w), "f"(vi.w)
        : "memory");
}

__device__ __forceinline__ void stcs1(ull* p, ull v) {
    asm volatile("st.global.cs.u64 [%0], %1;" :: "l"(p), "l"(v) : "memory");
}

// bits load with L2 evict_last cache hint (neutral but free; keeps input resident)
__device__ __forceinline__ int2 ld_bits(const int2* p, ull pol) {
    int2 v;
    asm("ld.global.nc.L2::cache_hint.v2.u32 {%0, %1}, [%2], %3;"
        : "=r"(v.x), "=r"(v.y) : "l"(p), "l"(pol));
    return v;
}

__global__ __launch_bounds__(THREADS, 8)
void qpsk_mod_kernel(const int* __restrict__ bits,
                     const float* __restrict__ rrc,
                     ull* __restrict__ out2)   // 1 complex per u64
{
    __shared__ __align__(16) float4 s_tab[4 * TROW4];
    __shared__ unsigned s_wre[NWORDS], s_wim[NWORDS];

    const int tid  = threadIdx.x;
    const int tile = blockIdx.x;       // 0..15
    const int row  = blockIdx.y;       // 0..255
    const int q0   = tile * SYMS_PER_BLOCK;

    ull pol;
    asm("createpolicy.fractional.L2::evict_last.b64 %0, 1.0;" : "=l"(pol));

    // ---- Build quad table: thread group (tid>>6) fills quad row qd,
    // entries (tid&63) + 64j. Taps load as warp-wide LDG broadcasts.
    {
        const int qd   = tid >> 6;          // quad row 0..3 -> phases 4qd..4qd+3
        const int ent0 = tid & 63;
        float t[4][8];
        #pragma unroll
        for (int d = 0; d < 4; d++) {
            int k0 = (71 - (4 * qd + d)) & 15;
            #pragma unroll
            for (int i = 0; i < 8; i++)
                t[d][i] = __ldg(rrc + k0 + 16 * i) * SCALE;
        }
        #pragma unroll
        for (int j = 0; j < 4; j++) {
            int b = ent0 + 64 * j;
            float v0 = 0.f, v1 = 0.f, v2 = 0.f, v3 = 0.f;
            #pragma unroll
            for (int i = 0; i < 8; i++) {
                float sg = ((b >> i) & 1) ? -1.f : 1.f;
                v0 = fmaf(sg, t[0][i], v0);
                v1 = fmaf(sg, t[1][i], v1);
                v2 = fmaf(sg, t[2][i], v2);
                v3 = fmaf(sg, t[3][i], v3);
            }
            s_tab[qd * TROW4 + b] = make_float4(v0, v1, v2, v3);
        }
    }

    // ---- Stage sign bits via ballot: word w holds symbols 32w..32w+31
    // (local t <-> symbol g = q0-4+t; out-of-range -> +1, fixed up below).
    const int2* bits2 = (const int2*)(bits + (long long)row * NUM_BITS);
    const unsigned lane = tid & 31;
    #pragma unroll
    for (int k = 0; k < 3; k++) {
        int t = k * THREADS + tid;
        int g = q0 - 4 + t;
        bool valid = (t < SYMS_PER_BLOCK + 8) && (g >= 0) && (g < NS);
        int2 bb = make_int2(0, 0);
        if (valid) bb = ld_bits(bits2 + g, pol);
        unsigned mre = __ballot_sync(0xFFFFFFFFu, valid && (bb.y & 1));
        unsigned mim = __ballot_sync(0xFFFFFFFFu, valid && (bb.x & 1));
        int wi = t >> 5;
        if (lane == 0 && wi < NWORDS) { s_wre[wi] = mre; s_wim[wi] = mim; }
    }
    __syncthreads();

    // ---- Main loop: fixed phase quad (4l..4l+3) per thread; one 32B store
    // per iteration; consecutive lanes write consecutive 32B (dense 1KB/warp).
    const int l    = tid & 3;
    const int grp  = tid >> 2;                 // 0..63
    const int flag = (l >= 2) ? 1 : 0;         // (phase >= 8)
    const float4* tabp = s_tab + l * TROW4;
    ull* out_base = out2 + (long long)row * UP_LEN + (long long)tile * OUTS_PER_BLOCK;

    #pragma unroll
    for (int it = 0; it < ITS; it++) {
        int u  = it * THREADS + tid;           // quad index 0..2047
        int s  = it * 64 + grp;                // symbol slot 0..511
        int w  = s + flag;                     // window start bit
        int wi = w >> 5, sh = w & 31;
        unsigned pre = __funnelshift_r(s_wre[wi], s_wre[wi + 1], sh) & 0xFF;
        unsigned pim = __funnelshift_r(s_wim[wi], s_wim[wi + 1], sh) & 0xFF;
        float4 vr = tabp[pre];                 // re for phases 4l..4l+3
        float4 vi = tabp[pim];                 // im for phases 4l..4l+3
        stcs8(out_base + 4 * u, vr, vi);       // 4 complex = 32B, one STG.256
    }

    // ---- Edge fixup: windows touching symbols outside [0,NS) assumed +1;
    // true value uses 0. Contaminated: n<64 and n>=UP_LEN-64. Recompute.
    // Barrier orders fixup stores after mainloop stores (R8 lesson).
    if (tile == 0 || tile == TILES - 1) {
        __syncthreads();
        if (tid < 64) {
            int n = (tile == 0) ? tid : (UP_LEN - 64 + tid);
            int p = n & 15, q = n >> 4;
            int k0   = (71 - p) & 15;
            int jmin = (p <= 7) ? -4 : -3;
            float re = 0.f, im = 0.f;
            #pragma unroll
            for (int i = 0; i < 8; i++) {
                int g = q + jmin + i;
                if ((unsigned)g < (unsigned)NS) {
                    int2 bb = ld_bits(bits2 + g, pol);
                    float t = __ldg(rrc + k0 + 16 * i) * SCALE;
                    re += (bb.y & 1) ? -t : t;
                    im += (bb.x & 1) ? -t : t;
                }
            }
            stcs1(out2 + (long long)row * UP_LEN + n, pack2(re, im));
        }
    }
}

extern "C" void kernel_launch(void* const* d_in, const int* in_sizes, int n_in,
                              void* d_out, int out_size)
{
    const int*   bits = (const int*)d_in[0];
    const float* rrc  = (const float*)d_in[1];
    ull*         out  = (ull*)d_out;

    dim3 grid(TILES, B_ROWS);                 // (16, 256)
    qpsk_mod_kernel<<<grid, THREADS>>>(bits, rrc, out);
}

// round 17
// speedup vs baseline: 1.1855x; 1.1855x over previous
#include <cuda_runtime.h>

// QPSK modulator: bits (256,16384) int32 -> Gray QPSK -> x16 zero-stuff
// (offset 8) -> RRC (K=128) -> out (256, 131072, 2) float32.
//
// FINAL (champion, R7): polyphase identity
//   y[16q+p] = sum_{i=0..7} sym[q+jmin+i] * rrc[k0+16i],
//   k0 = (71-p)&15, jmin = (p<=7) ? -4 : -3, scaled by sqrt(16).
// Symbols +-1/sqrt2 -> fold sqrt(16)/sqrt(2) into taps; each output is one
// of 256 signed-tap sums per phase -> 8x256 float2 table (even/odd phase)
// built per block. Mainloop: ballot sign bits -> funnel-shift 8-bit
// pattern -> 2x LDS.64 -> coalesced streaming STG.128 (st.global.cs).
//
// Measured map (bench = steady-state DRAM write drain of the 268MB output):
//   .cs STG.128 coalesced = 41.4us = 6.48 TB/s writes  <- chip write ceiling
//   default stores 47.6-49us; .wt 49.2; STG.256 49.3; strided STG 61.7;
//   >32 regs (occupancy loss) 62-82us; persistent grid 47.2; evict_last
//   on bits neutral (input already L2-resident across graph replays).

#define B_ROWS     256
#define NUM_BITS   16384
#define NS         8192
#define SPS        16
#define UP_LEN     (NS * SPS)          // 131072
#define SCALE      2.82842712474619f   // sqrt(16)/sqrt(2)

#define SYMS_PER_BLOCK   512
#define OUTS_PER_BLOCK   (SYMS_PER_BLOCK * SPS)     // 8192 complex
#define THREADS          256
#define ITS              16
#define TILES            (UP_LEN / OUTS_PER_BLOCK)  // 16
#define TROW             257                        // padded row stride
#define NWORDS           18                         // 520 sign bits

typedef unsigned long long ull;

__device__ __forceinline__ ull pack2(float lo, float hi) {
    ull v;
    asm("mov.b64 %0, {%1, %2};" : "=l"(v) : "f"(lo), "f"(hi));
    return v;
}

__device__ __forceinline__ void stcs2(ulonglong2* p, ull lo, ull hi) {
    asm volatile("st.global.cs.v2.u64 [%0], {%1, %2};"
                 :: "l"(p), "l"(lo), "l"(hi) : "memory");
}

__device__ __forceinline__ void stcs1(ull* p, ull v) {
    asm volatile("st.global.cs.u64 [%0], %1;" :: "l"(p), "l"(v) : "memory");
}

__global__ __launch_bounds__(THREADS, 8)
void qpsk_mod_kernel(const int* __restrict__ bits,
                     const float* __restrict__ rrc,
                     ulonglong2* __restrict__ out4)
{
    __shared__ __align__(16) float2 s_tab[8 * TROW];
    __shared__ unsigned s_wre[NWORDS], s_wim[NWORDS];

    const int tid  = threadIdx.x;
    const int tile = blockIdx.x;       // 0..15
    const int row  = blockIdx.y;       // 0..255
    const int q0   = tile * SYMS_PER_BLOCK;

    // ---- Build lookup table in-block: thread t fills row (t>>5), patterns
    // lane, lane+32, ..., lane+224. Taps load as warp-wide LDG broadcasts.
    {
        const int r    = tid >> 5;          // phase-pair row 0..7
        const int ln   = tid & 31;
        const int k0e  = (71 - 2 * r) & 15; // odd
        const int k0o  = k0e - 1;
        float te[8], to[8];
        #pragma unroll
        for (int i = 0; i < 8; i++) {
            te[i] = __ldg(rrc + k0e + 16 * i) * SCALE;
            to[i] = __ldg(rrc + k0o + 16 * i) * SCALE;
        }
        #pragma unroll
        for (int j = 0; j < 8; j++) {
            int b = ln + 32 * j;
            float se = 0.f, so = 0.f;
            #pragma unroll
            for (int i = 0; i < 8; i++) {
                float sg = ((b >> i) & 1) ? -1.f : 1.f;
                se = fmaf(sg, te[i], se);
                so = fmaf(sg, to[i], so);
            }
            s_tab[r * TROW + b] = make_float2(se, so);
        }
    }

    // ---- Stage sign bits via ballot: word w holds symbols 32w..32w+31
    // (local t <-> symbol g = q0-4+t; out-of-range -> +1, fixed up below).
    const int2* bits2 = (const int2*)(bits + (long long)row * NUM_BITS);
    const unsigned lane = tid & 31;
    #pragma unroll
    for (int k = 0; k < 3; k++) {
        int t = k * THREADS + tid;
        int g = q0 - 4 + t;
        bool valid = (t < SYMS_PER_BLOCK + 8) && (g >= 0) && (g < NS);
        int2 bb = make_int2(0, 0);
        if (valid) bb = bits2[g];
        unsigned mre = __ballot_sync(0xFFFFFFFFu, valid && (bb.y & 1));
        unsigned mim = __ballot_sync(0xFFFFFFFFu, valid && (bb.x & 1));
        int wi = t >> 5;
        if (lane == 0 && wi < NWORDS) { s_wre[wi] = mre; s_wim[wi] = mim; }
    }
    __syncthreads();

    // ---- Main loop: fixed phase pair (2l, 2l+1) per thread.
    const int l    = tid & 7;
    const int grp  = tid >> 3;                 // 0..31
    const int flag = (l >= 4) ? 1 : 0;         // (phase >= 8)
    const float2* tabp = s_tab + l * TROW;
    ulonglong2* out_base =
        out4 + (((long long)row * UP_LEN + (long long)tile * OUTS_PER_BLOCK) >> 1);

    #pragma unroll
    for (int it = 0; it < ITS; it++) {
        int pi = it * THREADS + tid;           // pair index 0..4095
        int w  = it * 32 + grp + flag;         // window start bit
        int wi = w >> 5, sh = w & 31;
        unsigned pre = __funnelshift_r(s_wre[wi], s_wre[wi + 1], sh) & 0xFF;
        unsigned pim = __funnelshift_r(s_wim[wi], s_wim[wi + 1], sh) & 0xFF;
        float2 vr = tabp[pre];                 // (re_even, re_odd)
        float2 vi = tabp[pim];                 // (im_even, im_odd)
        stcs2(out_base + pi, pack2(vr.x, vi.x), pack2(vr.y, vi.y));
    }

    // ---- Edge fixup: windows touching symbols outside [0,NS) assumed +1;
    // true value uses 0. Contaminated: n<64 and n>=UP_LEN-64. Recompute.
    // Barrier orders fixup stores after mainloop stores.
    if (tile == 0 || tile == TILES - 1) {
        __syncthreads();
        if (tid < 64) {
            int n = (tile == 0) ? tid : (UP_LEN - 64 + tid);
            int p = n & 15, q = n >> 4;
            int k0   = (71 - p) & 15;
            int jmin = (p <= 7) ? -4 : -3;
            float re = 0.f, im = 0.f;
            #pragma unroll
            for (int i = 0; i < 8; i++) {
                int g = q + jmin + i;
                if ((unsigned)g < (unsigned)NS) {
                    int2 bb = bits2[g];
                    float t = __ldg(rrc + k0 + 16 * i) * SCALE;
                    re += (bb.y & 1) ? -t : t;
                    im += (bb.x & 1) ? -t : t;
                }
            }
            ull* out2 = (ull*)out4;
            stcs1(out2 + (long long)row * UP_LEN + n, pack2(re, im));
        }
    }
}

extern "C" void kernel_launch(void* const* d_in, const int* in_sizes, int n_in,
                              void* d_out, int out_size)
{
    const int*   bits = (const int*)d_in[0];
    const float* rrc  = (const float*)d_in[1];
    ulonglong2*  out  = (ulonglong2*)d_out;

    dim3 grid(TILES, B_ROWS);                 // (16, 256)
    qpsk_mod_kernel<<<grid, THREADS>>>(bits, rrc, out);
}